// round 1
// baseline (speedup 1.0000x reference)
#include <cuda_runtime.h>

#define BDIM 8
#define NDIM 2048
#define DDIM 512
#define P_ASEM 0.6f

// Scratch for row scores: si[b*N+i] (includes bias), sj[b*N+j]
__device__ float g_si[BDIM * NDIM];
__device__ float g_sj[BDIM * NDIM];

// Kernel 1: one warp per row. Computes si = x_row . Wi + b, sj = x_row . Wj.
// 16384 rows total; vectorized float4 loads (512 floats = 128 float4 per row,
// 4 float4 per lane).
__global__ void row_dots_kernel(const float* __restrict__ x,
                                const float* __restrict__ W,
                                const float* __restrict__ bias) {
    int warp_id = (blockIdx.x * blockDim.x + threadIdx.x) >> 5;
    int lane = threadIdx.x & 31;
    if (warp_id >= BDIM * NDIM) return;

    const float4* xr = reinterpret_cast<const float4*>(x + (size_t)warp_id * DDIM);
    const float4* Wi = reinterpret_cast<const float4*>(W);
    const float4* Wj = reinterpret_cast<const float4*>(W + DDIM);

    float si = 0.f, sj = 0.f;
#pragma unroll
    for (int k = 0; k < DDIM / 4 / 32; k++) {
        int d4 = lane + k * 32;
        float4 xv = xr[d4];
        float4 wi = Wi[d4];
        float4 wj = Wj[d4];
        si += xv.x * wi.x + xv.y * wi.y + xv.z * wi.z + xv.w * wi.w;
        sj += xv.x * wj.x + xv.y * wj.y + xv.z * wj.z + xv.w * wj.w;
    }
#pragma unroll
    for (int o = 16; o; o >>= 1) {
        si += __shfl_down_sync(0xffffffffu, si, o);
        sj += __shfl_down_sync(0xffffffffu, sj, o);
    }
    if (lane == 0) {
        g_si[warp_id] = si + bias[0];
        g_sj[warp_id] = sj;
    }
}

__device__ __forceinline__ float fsig(float t) {
    return 1.0f / (1.0f + __expf(-t));
}

// Kernel 2: elementwise fuse, float4 vectorized.
// out[b,i,j] = P * sigmoid(si[b,i] + sj[b,j]) + (1-P) * adj[b,i,j]
__global__ void fuse_kernel(const float* __restrict__ adj,
                            float* __restrict__ out) {
    unsigned idx = blockIdx.x * blockDim.x + threadIdx.x;  // float4 index
    const unsigned total4 = (unsigned)BDIM * NDIM * NDIM / 4;
    if (idx >= total4) return;

    unsigned e = idx * 4u;                 // element index (< 2^25, fits)
    unsigned b = e >> 22;                  // / (2048*2048)
    unsigned rem = e & ((1u << 22) - 1u);
    unsigned i = rem >> 11;                // / 2048
    unsigned j = rem & 2047u;

    float si = g_si[(b << 11) + i];
    const float* sjp = g_sj + (b << 11) + j;

    float4 a = reinterpret_cast<const float4*>(adj)[idx];
    float4 o;
    o.x = P_ASEM * fsig(si + sjp[0]) + (1.0f - P_ASEM) * a.x;
    o.y = P_ASEM * fsig(si + sjp[1]) + (1.0f - P_ASEM) * a.y;
    o.z = P_ASEM * fsig(si + sjp[2]) + (1.0f - P_ASEM) * a.z;
    o.w = P_ASEM * fsig(si + sjp[3]) + (1.0f - P_ASEM) * a.w;
    reinterpret_cast<float4*>(out)[idx] = o;
}

extern "C" void kernel_launch(void* const* d_in, const int* in_sizes, int n_in,
                              void* d_out, int out_size) {
    const float* x   = (const float*)d_in[0];  // (8, 2048, 512)
    const float* adj = (const float*)d_in[1];  // (8, 2048, 2048)
    const float* W   = (const float*)d_in[2];  // (1, 1024)
    const float* b   = (const float*)d_in[3];  // (1,)
    float* out = (float*)d_out;

    // Kernel 1: 16384 rows, 8 warps/block -> 2048 blocks
    {
        int threads = 256;
        int rows = BDIM * NDIM;
        int warps_per_block = threads / 32;
        int blocks = (rows + warps_per_block - 1) / warps_per_block;
        row_dots_kernel<<<blocks, threads>>>(x, W, b);
    }
    // Kernel 2: 33.5M elements / 4 = 8.39M float4 threads
    {
        int threads = 256;
        unsigned total4 = (unsigned)BDIM * NDIM * NDIM / 4;
        unsigned blocks = (total4 + threads - 1) / threads;
        fuse_kernel<<<blocks, threads>>>(adj, out);
    }
}

// round 2
// speedup vs baseline: 1.0900x; 1.0900x over previous
#include <cuda_runtime.h>

#define BDIM 8
#define NDIM 2048
#define DDIM 512
#define P_ASEM 0.6f

// Scratch for row scores: si[b*N+i] (includes bias), sj[b*N+j]
__device__ float g_si[BDIM * NDIM];
__device__ float g_sj[BDIM * NDIM];

// Kernel 1: one warp per row. Computes si = x_row . Wi + b, sj = x_row . Wj.
__global__ void row_dots_kernel(const float* __restrict__ x,
                                const float* __restrict__ W,
                                const float* __restrict__ bias) {
    int warp_id = (blockIdx.x * blockDim.x + threadIdx.x) >> 5;
    int lane = threadIdx.x & 31;
    if (warp_id >= BDIM * NDIM) return;

    const float4* xr = reinterpret_cast<const float4*>(x + (size_t)warp_id * DDIM);
    const float4* Wi = reinterpret_cast<const float4*>(W);
    const float4* Wj = reinterpret_cast<const float4*>(W + DDIM);

    float si = 0.f, sj = 0.f;
#pragma unroll
    for (int k = 0; k < DDIM / 4 / 32; k++) {
        int d4 = lane + k * 32;
        float4 xv = xr[d4];
        float4 wi = Wi[d4];
        float4 wj = Wj[d4];
        si += xv.x * wi.x + xv.y * wi.y + xv.z * wi.z + xv.w * wi.w;
        sj += xv.x * wj.x + xv.y * wj.y + xv.z * wj.z + xv.w * wj.w;
    }
#pragma unroll
    for (int o = 16; o; o >>= 1) {
        si += __shfl_down_sync(0xffffffffu, si, o);
        sj += __shfl_down_sync(0xffffffffu, sj, o);
    }
    if (lane == 0) {
        g_si[warp_id] = si + bias[0];
        g_sj[warp_id] = sj;
    }
}

__device__ __forceinline__ float fsig(float t) {
    return 1.0f / (1.0f + __expf(-t));
}

// Kernel 2: elementwise fuse.
// Each thread handles 4 float4s (16 elements), all loads front-batched for MLP.
// Block covers 1024 consecutive float4s (4096 floats). Grid = 8192 exactly.
__global__ void __launch_bounds__(256) fuse_kernel(const float* __restrict__ adj,
                                                   float* __restrict__ out) {
    unsigned base = blockIdx.x * 1024u + threadIdx.x;  // first float4 index

    float4 a[4];
    float4 sjv[4];
    float  siv[4];

#pragma unroll
    for (int k = 0; k < 4; k++) {
        unsigned idx = base + k * 256u;
        unsigned e = idx * 4u;                   // element index, < 2^25
        unsigned b = e >> 22;                    // / (2048*2048)
        unsigned rem = e & ((1u << 22) - 1u);
        unsigned i = rem >> 11;                  // / 2048
        unsigned j = rem & 2047u;                // 4-aligned

        a[k]   = __ldg(reinterpret_cast<const float4*>(adj) + idx);
        sjv[k] = *reinterpret_cast<const float4*>(g_sj + (b << 11) + j);
        siv[k] = g_si[(b << 11) + i];
    }

#pragma unroll
    for (int k = 0; k < 4; k++) {
        unsigned idx = base + k * 256u;
        float si = siv[k];
        float4 o;
        o.x = fmaf(P_ASEM, fsig(si + sjv[k].x), (1.0f - P_ASEM) * a[k].x);
        o.y = fmaf(P_ASEM, fsig(si + sjv[k].y), (1.0f - P_ASEM) * a[k].y);
        o.z = fmaf(P_ASEM, fsig(si + sjv[k].z), (1.0f - P_ASEM) * a[k].z);
        o.w = fmaf(P_ASEM, fsig(si + sjv[k].w), (1.0f - P_ASEM) * a[k].w);
        reinterpret_cast<float4*>(out)[idx] = o;
    }
}

extern "C" void kernel_launch(void* const* d_in, const int* in_sizes, int n_in,
                              void* d_out, int out_size) {
    const float* x   = (const float*)d_in[0];  // (8, 2048, 512)
    const float* adj = (const float*)d_in[1];  // (8, 2048, 2048)
    const float* W   = (const float*)d_in[2];  // (1, 1024)
    const float* b   = (const float*)d_in[3];  // (1,)
    float* out = (float*)d_out;

    // Kernel 1: 16384 rows, 8 warps/block -> 2048 blocks
    {
        int threads = 256;
        int rows = BDIM * NDIM;
        int warps_per_block = threads / 32;
        int blocks = (rows + warps_per_block - 1) / warps_per_block;
        row_dots_kernel<<<blocks, threads>>>(x, W, b);
    }
    // Kernel 2: 8388608 float4s / (256 threads * 4 per thread) = 8192 blocks
    {
        fuse_kernel<<<8192, 256>>>(adj, out);
    }
}